// round 3
// baseline (speedup 1.0000x reference)
#include <cuda_runtime.h>

// ---------------- problem constants ----------------
#define NMAX 100000
#define EMAX 600000
#define FIN  128
#define FHID 128
#define FOUT 64

// ---------------- scratch (static device globals; no allocs) ----------------
__device__ __align__(16) float g_hn[(size_t)NMAX * FHID];   // hn = (X@W)*dinv[row]
__device__ __align__(16) float g_x2[(size_t)NMAX * FHID];   // layer-2 input
__device__ __align__(16) float g_dinv[NMAX];
__device__ int   g_count[NMAX];
__device__ int   g_offsets[NMAX + 1];
__device__ int   g_cursor[NMAX];
__device__ int   g_srcsorted[EMAX];
__device__ int   g_blocksums[128];

// ---------------- degree / CSR build ----------------
__global__ void k_zero_count(int n) {
    int i = blockIdx.x * blockDim.x + threadIdx.x;
    if (i < n) g_count[i] = 0;
}

// edge_index is int32, layout [2, E]: src = ei[e], dst = ei[E + e]
__global__ void k_hist(const int* __restrict__ ei, int n_edges, int n_nodes) {
    int e = blockIdx.x * blockDim.x + threadIdx.x;
    if (e < n_edges) {
        int d = ei[n_edges + e];
        if ((unsigned)d < (unsigned)n_nodes) atomicAdd(&g_count[d], 1);
    }
}

__global__ void k_dinv(int n) {
    int i = blockIdx.x * blockDim.x + threadIdx.x;
    if (i < n) g_dinv[i] = rsqrtf((float)(g_count[i] + 1));  // +1 self loop
}

// scan phase A: per-block sum of 1024 counts
__global__ void k_scanA(int n) {
    __shared__ int s[256];
    int t = threadIdx.x;
    int base = blockIdx.x * 1024;
    int v = 0;
    #pragma unroll
    for (int k = 0; k < 4; k++) {
        int i = base + t * 4 + k;
        if (i < n) v += g_count[i];
    }
    s[t] = v;
    __syncthreads();
    for (int off = 128; off > 0; off >>= 1) {
        if (t < off) s[t] += s[t + off];
        __syncthreads();
    }
    if (t == 0) g_blocksums[blockIdx.x] = s[0];
}

// scan phase B: serial exclusive scan of block sums (nb <= 128) + tail offset
__global__ void k_scanB(int nb, int n_nodes, int n_edges) {
    if (threadIdx.x == 0) {
        int run = 0;
        for (int b = 0; b < nb; b++) {
            int v = g_blocksums[b];
            g_blocksums[b] = run;
            run += v;
        }
        g_offsets[n_nodes] = n_edges;
    }
}

// scan phase C: exclusive scan within block, add block offset, write offsets+cursor
__global__ void k_scanC(int n) {
    __shared__ int s[256];
    int t = threadIdx.x;
    int base = blockIdx.x * 1024;
    int vals[4];
    int tsum = 0;
    #pragma unroll
    for (int k = 0; k < 4; k++) {
        int i = base + t * 4 + k;
        vals[k] = (i < n) ? g_count[i] : 0;
        tsum += vals[k];
    }
    s[t] = tsum;
    __syncthreads();
    // Hillis-Steele inclusive scan
    for (int off = 1; off < 256; off <<= 1) {
        int x = (t >= off) ? s[t - off] : 0;
        __syncthreads();
        s[t] += x;
        __syncthreads();
    }
    int texcl = s[t] - tsum + g_blocksums[blockIdx.x];
    int run = 0;
    #pragma unroll
    for (int k = 0; k < 4; k++) {
        int i = base + t * 4 + k;
        if (i < n) {
            int o = texcl + run;
            g_offsets[i] = o;
            g_cursor[i]  = o;
        }
        run += vals[k];
    }
}

__global__ void k_fill(const int* __restrict__ ei, int n_edges, int n_nodes) {
    int e = blockIdx.x * blockDim.x + threadIdx.x;
    if (e < n_edges) {
        int srcv = ei[e];
        int d    = ei[n_edges + e];
        if ((unsigned)d < (unsigned)n_nodes && (unsigned)srcv < (unsigned)n_nodes) {
            int p = atomicAdd(&g_cursor[d], 1);
            g_srcsorted[p] = srcv;
        }
    }
}

// ---------------- SGEMM with fused dinv epilogue ----------------
// g_hn[m,n] = g_dinv[m] * sum_k A[m,k]*B[k,n]
// A = external pointer (SRC=0) or g_x2 (SRC=1)
// 64x64 tile, TK=16, 256 threads, 4x4 per thread
template <int SRC>
__global__ void k_sgemm_dinv(const float* __restrict__ Aext,
                             const float* __restrict__ B,
                             int M, int N, int K) {
    const float* __restrict__ A = (SRC == 0) ? Aext : g_x2;
    const int TM = 64, TN = 64, TK = 16;
    __shared__ float As[TM][TK];
    __shared__ float Bs[TK][TN];
    int tid = threadIdx.x;
    int tx = tid % 16, ty = tid / 16;
    int row0 = blockIdx.y * TM, col0 = blockIdx.x * TN;

    float acc[4][4] = {};

    for (int k0 = 0; k0 < K; k0 += TK) {
        #pragma unroll
        for (int i = 0; i < 4; i++) {
            int idx = tid + i * 256;
            int m = idx / TK, kk = idx % TK;
            int gr = row0 + m;
            As[m][kk] = (gr < M) ? A[(size_t)gr * K + k0 + kk] : 0.0f;
        }
        #pragma unroll
        for (int i = 0; i < 4; i++) {
            int idx = tid + i * 256;
            int kk = idx / TN, nn = idx % TN;
            Bs[kk][nn] = B[(size_t)(k0 + kk) * N + col0 + nn];
        }
        __syncthreads();

        #pragma unroll
        for (int kk = 0; kk < TK; kk++) {
            float a[4];
            #pragma unroll
            for (int i = 0; i < 4; i++) a[i] = As[ty * 4 + i][kk];
            float4 b4 = *reinterpret_cast<const float4*>(&Bs[kk][tx * 4]);
            #pragma unroll
            for (int i = 0; i < 4; i++) {
                acc[i][0] += a[i] * b4.x;
                acc[i][1] += a[i] * b4.y;
                acc[i][2] += a[i] * b4.z;
                acc[i][3] += a[i] * b4.w;
            }
        }
        __syncthreads();
    }

    #pragma unroll
    for (int i = 0; i < 4; i++) {
        int r = row0 + ty * 4 + i;
        if (r < M) {
            float dv = g_dinv[r];
            float4 o;
            o.x = acc[i][0] * dv;
            o.y = acc[i][1] * dv;
            o.z = acc[i][2] * dv;
            o.w = acc[i][3] * dv;
            *reinterpret_cast<float4*>(&g_hn[(size_t)r * N + col0 + tx * 4]) = o;
        }
    }
}

// ---------------- aggregation: one warp per node, gather + finalize ----------------
// x2[d] = relu( dinv[d]*(hn[d] + sum_{s in N(d)} hn[s]) + bias )   (F=128)
__global__ void k_agg128(const float* __restrict__ bias, int n_nodes) {
    int warp = (blockIdx.x * blockDim.x + threadIdx.x) >> 5;
    int lane = threadIdx.x & 31;
    if (warp >= n_nodes) return;
    int d = warp;
    const float* hn = g_hn;
    float4 acc = *reinterpret_cast<const float4*>(hn + (size_t)d * 128 + lane * 4);
    int e0 = g_offsets[d], e1 = g_offsets[d + 1];
    for (int e = e0; e < e1; e++) {
        int s = g_srcsorted[e];
        float4 hv = *reinterpret_cast<const float4*>(hn + (size_t)s * 128 + lane * 4);
        acc.x += hv.x; acc.y += hv.y; acc.z += hv.z; acc.w += hv.w;
    }
    float dv = g_dinv[d];
    float4 bv = *reinterpret_cast<const float4*>(bias + lane * 4);
    float4 o;
    o.x = fmaxf(acc.x * dv + bv.x, 0.f);
    o.y = fmaxf(acc.y * dv + bv.y, 0.f);
    o.z = fmaxf(acc.z * dv + bv.z, 0.f);
    o.w = fmaxf(acc.w * dv + bv.w, 0.f);
    *reinterpret_cast<float4*>(g_x2 + (size_t)d * 128 + lane * 4) = o;
}

// out[d] = dinv[d]*(hn[d] + sum hn[s]) + bias   (F=64, no relu)
__global__ void k_agg64(const float* __restrict__ bias,
                        float* __restrict__ out, int n_nodes) {
    int warp = (blockIdx.x * blockDim.x + threadIdx.x) >> 5;
    int lane = threadIdx.x & 31;
    if (warp >= n_nodes) return;
    int d = warp;
    const float* hn = g_hn;
    float2 acc = *reinterpret_cast<const float2*>(hn + (size_t)d * 64 + lane * 2);
    int e0 = g_offsets[d], e1 = g_offsets[d + 1];
    for (int e = e0; e < e1; e++) {
        int s = g_srcsorted[e];
        float2 hv = *reinterpret_cast<const float2*>(hn + (size_t)s * 64 + lane * 2);
        acc.x += hv.x; acc.y += hv.y;
    }
    float dv = g_dinv[d];
    float2 bv = *reinterpret_cast<const float2*>(bias + lane * 2);
    float2 o;
    o.x = acc.x * dv + bv.x;
    o.y = acc.y * dv + bv.y;
    *reinterpret_cast<float2*>(out + (size_t)d * 64 + lane * 2) = o;
}

// ---------------- launch ----------------
extern "C" void kernel_launch(void* const* d_in, const int* in_sizes, int n_in,
                              void* d_out, int out_size) {
    const float* x  = (const float*)d_in[0];
    const int*   ei = (const int*)d_in[1];     // int32 (JAX x64 disabled demotes int64)
    const float* W1 = (const float*)d_in[2];
    const float* b1 = (const float*)d_in[3];
    const float* W2 = (const float*)d_in[4];
    const float* b2 = (const float*)d_in[5];
    float* out = (float*)d_out;

    int n_nodes = in_sizes[0] / FIN;       // 100000
    int n_edges = in_sizes[1] / 2;         // 600000

    int nb_nodes = (n_nodes + 255) / 256;
    int nb_edges = (n_edges + 255) / 256;
    int nb_scan  = (n_nodes + 1023) / 1024;

    // ---- CSR build + degrees ----
    k_zero_count<<<nb_nodes, 256>>>(n_nodes);
    k_hist<<<nb_edges, 256>>>(ei, n_edges, n_nodes);
    k_dinv<<<nb_nodes, 256>>>(n_nodes);
    k_scanA<<<nb_scan, 256>>>(n_nodes);
    k_scanB<<<1, 32>>>(nb_scan, n_nodes, n_edges);
    k_scanC<<<nb_scan, 256>>>(n_nodes);
    k_fill<<<nb_edges, 256>>>(ei, n_edges, n_nodes);

    // ---- layer 1: hn = (x@W1)*dinv ; x2 = relu(dinv*agg + b1) ----
    {
        dim3 grid(FHID / 64, (n_nodes + 63) / 64);
        k_sgemm_dinv<0><<<grid, 256>>>(x, W1, n_nodes, FHID, FIN);
        int nb_agg = (n_nodes * 32 + 255) / 256;
        k_agg128<<<nb_agg, 256>>>(b1, n_nodes);
    }

    // ---- layer 2: hn = (x2@W2)*dinv ; out = dinv*agg + b2 ----
    {
        dim3 grid(FOUT / 64, (n_nodes + 63) / 64);
        k_sgemm_dinv<1><<<grid, 256>>>(nullptr, W2, n_nodes, FOUT, FHID);
        int nb_agg = (n_nodes * 32 + 255) / 256;
        k_agg64<<<nb_agg, 256>>>(b2, out, n_nodes);
    }
}

// round 4
// speedup vs baseline: 1.5211x; 1.5211x over previous
#include <cuda_runtime.h>
#include <cstdint>

// ---------------- problem constants ----------------
#define NMAX 100000
#define EMAX 600000
#define FIN  128
#define FHID 128
#define FOUT 64

// ---------------- scratch (static device globals; no allocs) ----------------
__device__ __align__(16) float g_hn[(size_t)NMAX * FHID];   // hn = (X@W)*dinv[row]
__device__ __align__(16) float g_x2[(size_t)NMAX * FHID];   // layer-2 input
__device__ __align__(16) float g_dinv[NMAX];
__device__ int   g_count[NMAX];
__device__ int   g_offsets[NMAX + 1];
__device__ int   g_cursor[NMAX];
__device__ int   g_srcsorted[EMAX];
__device__ int   g_blocksums[128];

// ---------------- degree / CSR build ----------------
__global__ void k_zero_count(int n) {
    int i = blockIdx.x * blockDim.x + threadIdx.x;
    if (i < n) g_count[i] = 0;
}

// edge_index is int32, layout [2, E]: src = ei[e], dst = ei[E + e]
__global__ void k_hist(const int* __restrict__ ei, int n_edges, int n_nodes) {
    int e = blockIdx.x * blockDim.x + threadIdx.x;
    if (e < n_edges) {
        int d = ei[n_edges + e];
        if ((unsigned)d < (unsigned)n_nodes) atomicAdd(&g_count[d], 1);
    }
}

__global__ void k_dinv(int n) {
    int i = blockIdx.x * blockDim.x + threadIdx.x;
    if (i < n) g_dinv[i] = rsqrtf((float)(g_count[i] + 1));  // +1 self loop
}

// scan phase A: per-block sum of 1024 counts
__global__ void k_scanA(int n) {
    __shared__ int s[256];
    int t = threadIdx.x;
    int base = blockIdx.x * 1024;
    int v = 0;
    #pragma unroll
    for (int k = 0; k < 4; k++) {
        int i = base + t * 4 + k;
        if (i < n) v += g_count[i];
    }
    s[t] = v;
    __syncthreads();
    for (int off = 128; off > 0; off >>= 1) {
        if (t < off) s[t] += s[t + off];
        __syncthreads();
    }
    if (t == 0) g_blocksums[blockIdx.x] = s[0];
}

// scan phase B: serial exclusive scan of block sums (nb <= 128) + tail offset
__global__ void k_scanB(int nb, int n_nodes, int n_edges) {
    if (threadIdx.x == 0) {
        int run = 0;
        for (int b = 0; b < nb; b++) {
            int v = g_blocksums[b];
            g_blocksums[b] = run;
            run += v;
        }
        g_offsets[n_nodes] = n_edges;
    }
}

// scan phase C: exclusive scan within block, add block offset, write offsets+cursor
__global__ void k_scanC(int n) {
    __shared__ int s[256];
    int t = threadIdx.x;
    int base = blockIdx.x * 1024;
    int vals[4];
    int tsum = 0;
    #pragma unroll
    for (int k = 0; k < 4; k++) {
        int i = base + t * 4 + k;
        vals[k] = (i < n) ? g_count[i] : 0;
        tsum += vals[k];
    }
    s[t] = tsum;
    __syncthreads();
    for (int off = 1; off < 256; off <<= 1) {
        int x = (t >= off) ? s[t - off] : 0;
        __syncthreads();
        s[t] += x;
        __syncthreads();
    }
    int texcl = s[t] - tsum + g_blocksums[blockIdx.x];
    int run = 0;
    #pragma unroll
    for (int k = 0; k < 4; k++) {
        int i = base + t * 4 + k;
        if (i < n) {
            int o = texcl + run;
            g_offsets[i] = o;
            g_cursor[i]  = o;
        }
        run += vals[k];
    }
}

__global__ void k_fill(const int* __restrict__ ei, int n_edges, int n_nodes) {
    int e = blockIdx.x * blockDim.x + threadIdx.x;
    if (e < n_edges) {
        int srcv = ei[e];
        int d    = ei[n_edges + e];
        if ((unsigned)d < (unsigned)n_nodes && (unsigned)srcv < (unsigned)n_nodes) {
            int p = atomicAdd(&g_cursor[d], 1);
            g_srcsorted[p] = srcv;
        }
    }
}

// ---------------- TF32 tensor-core GEMM with fused dinv epilogue ----------------
// g_hn[m,n] = g_dinv[m] * sum_k A[m,k]*B[k,n]    (A,B rounded to tf32)
// A = external pointer (SRC=0) or g_x2 (SRC=1). BN = N (128 or 64), K multiple of 32.
// Block: 128 rows x BN cols. 8 warps = 4(M) x 2(N). Warp tile: 32 x BN/2.
// mma.sync.m16n8k8 tf32: per warp 2 m-frags x (BN/16) n-frags.

__device__ __forceinline__ float to_tf32(float x) {
    uint32_t u;
    asm("cvt.rna.tf32.f32 %0, %1;" : "=r"(u) : "f"(x));
    return __uint_as_float(u);
}

__device__ __forceinline__ void mma_tf32(float c[4], const float a[4], float b0, float b1) {
    uint32_t const* A = reinterpret_cast<uint32_t const*>(a);
    uint32_t B0 = __float_as_uint(b0), B1 = __float_as_uint(b1);
    asm volatile(
        "mma.sync.aligned.m16n8k8.row.col.f32.tf32.tf32.f32 "
        "{%0,%1,%2,%3}, {%4,%5,%6,%7}, {%8,%9}, {%0,%1,%2,%3};"
        : "+f"(c[0]), "+f"(c[1]), "+f"(c[2]), "+f"(c[3])
        : "r"(A[0]), "r"(A[1]), "r"(A[2]), "r"(A[3]), "r"(B0), "r"(B1));
}

template <int BN, int SRC>
__global__ void __launch_bounds__(256)
k_mma_dinv(const float* __restrict__ Aext, const float* __restrict__ Bg,
           int M, int K) {
    const float* __restrict__ A = (SRC == 0) ? Aext : g_x2;
    const int KC = 32;
    const int APITCH = KC + 4;        // 36: conflict-free for frag reads
    const int BPITCH = BN + 8;        // k-stride*4 mod 32 = 8 -> conflict-free
    __shared__ float As[128 * APITCH];
    __shared__ float Bs[KC * BPITCH];

    int tid  = threadIdx.x;
    int warp = tid >> 5, lane = tid & 31;
    int wm = warp & 3;                 // M position (0..3)
    int wn = warp >> 2;                // N position (0..1)
    const int WNT = BN / 2;            // warp n-extent
    const int NF  = WNT / 8;           // n-fragments per warp
    int g  = lane >> 2;                // group id (0..7)
    int tg = lane & 3;                 // thread-in-group (0..3)
    int row0 = blockIdx.x * 128;

    float acc[2][NF][4];
    #pragma unroll
    for (int i = 0; i < 2; i++)
        #pragma unroll
        for (int j = 0; j < NF; j++)
            #pragma unroll
            for (int q = 0; q < 4; q++) acc[i][j][q] = 0.0f;

    for (int k0 = 0; k0 < K; k0 += KC) {
        // ---- stage A chunk [128 x 32], tf32-rounded ----
        {
            int r = tid >> 3;              // 0..31
            int c = (tid & 7) * 4;         // 0..28
            #pragma unroll
            for (int i = 0; i < 4; i++) {
                int rr = r + i * 32;
                float4 v = make_float4(0.f, 0.f, 0.f, 0.f);
                if (row0 + rr < M)
                    v = *reinterpret_cast<const float4*>(A + (size_t)(row0 + rr) * K + k0 + c);
                v.x = to_tf32(v.x); v.y = to_tf32(v.y);
                v.z = to_tf32(v.z); v.w = to_tf32(v.w);
                *reinterpret_cast<float4*>(&As[rr * APITCH + c]) = v;
            }
        }
        // ---- stage B chunk [32 x BN], tf32-rounded ----
        {
            const int TPR = BN / 4;        // threads per row
            int kr = tid / TPR;
            int bc = (tid % TPR) * 4;
            const int KSTEP = 256 / TPR;
            #pragma unroll
            for (int i = 0; i < KC / KSTEP; i++) {
                int kk = kr + i * KSTEP;
                float4 v = *reinterpret_cast<const float4*>(Bg + (size_t)(k0 + kk) * BN + bc);
                v.x = to_tf32(v.x); v.y = to_tf32(v.y);
                v.z = to_tf32(v.z); v.w = to_tf32(v.w);
                *reinterpret_cast<float4*>(&Bs[kk * BPITCH + bc]) = v;
            }
        }
        __syncthreads();

        #pragma unroll
        for (int ks = 0; ks < KC; ks += 8) {
            float a[2][4];
            #pragma unroll
            for (int mf = 0; mf < 2; mf++) {
                int ar = wm * 32 + mf * 16;
                a[mf][0] = As[(ar + g)     * APITCH + ks + tg];
                a[mf][1] = As[(ar + g + 8) * APITCH + ks + tg];
                a[mf][2] = As[(ar + g)     * APITCH + ks + tg + 4];
                a[mf][3] = As[(ar + g + 8) * APITCH + ks + tg + 4];
            }
            #pragma unroll
            for (int nf = 0; nf < NF; nf++) {
                int bn0 = wn * WNT + nf * 8;
                float b0 = Bs[(ks + tg)     * BPITCH + bn0 + g];
                float b1 = Bs[(ks + tg + 4) * BPITCH + bn0 + g];
                #pragma unroll
                for (int mf = 0; mf < 2; mf++)
                    mma_tf32(acc[mf][nf], a[mf], b0, b1);
            }
        }
        __syncthreads();
    }

    // ---- epilogue: scale by dinv, write g_hn ----
    #pragma unroll
    for (int mf = 0; mf < 2; mf++) {
        int r0 = row0 + wm * 32 + mf * 16 + g;
        int r1 = r0 + 8;
        float d0 = (r0 < M) ? g_dinv[r0] : 0.f;
        float d1 = (r1 < M) ? g_dinv[r1] : 0.f;
        #pragma unroll
        for (int nf = 0; nf < NF; nf++) {
            int cc = wn * WNT + nf * 8 + tg * 2;
            if (r0 < M) {
                g_hn[(size_t)r0 * BN + cc]     = acc[mf][nf][0] * d0;
                g_hn[(size_t)r0 * BN + cc + 1] = acc[mf][nf][1] * d0;
            }
            if (r1 < M) {
                g_hn[(size_t)r1 * BN + cc]     = acc[mf][nf][2] * d1;
                g_hn[(size_t)r1 * BN + cc + 1] = acc[mf][nf][3] * d1;
            }
        }
    }
}

// ---------------- aggregation: one warp per node, gather + finalize ----------------
// x2[d] = relu( dinv[d]*(hn[d] + sum_{s in N(d)} hn[s]) + bias )   (F=128)
__global__ void k_agg128(const float* __restrict__ bias, int n_nodes) {
    int warp = (blockIdx.x * blockDim.x + threadIdx.x) >> 5;
    int lane = threadIdx.x & 31;
    if (warp >= n_nodes) return;
    int d = warp;
    const float* hn = g_hn;
    float4 acc = *reinterpret_cast<const float4*>(hn + (size_t)d * 128 + lane * 4);
    int e0 = g_offsets[d], e1 = g_offsets[d + 1];
    for (int e = e0; e < e1; e++) {
        int s = g_srcsorted[e];
        float4 hv = *reinterpret_cast<const float4*>(hn + (size_t)s * 128 + lane * 4);
        acc.x += hv.x; acc.y += hv.y; acc.z += hv.z; acc.w += hv.w;
    }
    float dv = g_dinv[d];
    float4 bv = *reinterpret_cast<const float4*>(bias + lane * 4);
    float4 o;
    o.x = fmaxf(acc.x * dv + bv.x, 0.f);
    o.y = fmaxf(acc.y * dv + bv.y, 0.f);
    o.z = fmaxf(acc.z * dv + bv.z, 0.f);
    o.w = fmaxf(acc.w * dv + bv.w, 0.f);
    *reinterpret_cast<float4*>(g_x2 + (size_t)d * 128 + lane * 4) = o;
}

// out[d] = dinv[d]*(hn[d] + sum hn[s]) + bias   (F=64, no relu)
__global__ void k_agg64(const float* __restrict__ bias,
                        float* __restrict__ out, int n_nodes) {
    int warp = (blockIdx.x * blockDim.x + threadIdx.x) >> 5;
    int lane = threadIdx.x & 31;
    if (warp >= n_nodes) return;
    int d = warp;
    const float* hn = g_hn;
    float2 acc = *reinterpret_cast<const float2*>(hn + (size_t)d * 64 + lane * 2);
    int e0 = g_offsets[d], e1 = g_offsets[d + 1];
    for (int e = e0; e < e1; e++) {
        int s = g_srcsorted[e];
        float2 hv = *reinterpret_cast<const float2*>(hn + (size_t)s * 64 + lane * 2);
        acc.x += hv.x; acc.y += hv.y;
    }
    float dv = g_dinv[d];
    float2 bv = *reinterpret_cast<const float2*>(bias + lane * 2);
    float2 o;
    o.x = acc.x * dv + bv.x;
    o.y = acc.y * dv + bv.y;
    *reinterpret_cast<float2*>(out + (size_t)d * 64 + lane * 2) = o;
}

// ---------------- launch ----------------
extern "C" void kernel_launch(void* const* d_in, const int* in_sizes, int n_in,
                              void* d_out, int out_size) {
    const float* x  = (const float*)d_in[0];
    const int*   ei = (const int*)d_in[1];     // int32 [2, E]
    const float* W1 = (const float*)d_in[2];
    const float* b1 = (const float*)d_in[3];
    const float* W2 = (const float*)d_in[4];
    const float* b2 = (const float*)d_in[5];
    float* out = (float*)d_out;

    int n_nodes = in_sizes[0] / FIN;       // 100000
    int n_edges = in_sizes[1] / 2;         // 600000

    int nb_nodes = (n_nodes + 255) / 256;
    int nb_edges = (n_edges + 255) / 256;
    int nb_scan  = (n_nodes + 1023) / 1024;

    // ---- CSR build + degrees ----
    k_zero_count<<<nb_nodes, 256>>>(n_nodes);
    k_hist<<<nb_edges, 256>>>(ei, n_edges, n_nodes);
    k_dinv<<<nb_nodes, 256>>>(n_nodes);
    k_scanA<<<nb_scan, 256>>>(n_nodes);
    k_scanB<<<1, 32>>>(nb_scan, n_nodes, n_edges);
    k_scanC<<<nb_scan, 256>>>(n_nodes);
    k_fill<<<nb_edges, 256>>>(ei, n_edges, n_nodes);

    int nb_gemm = (n_nodes + 127) / 128;
    int nb_agg  = (n_nodes * 32 + 255) / 256;

    // ---- layer 1: hn = tf32(x@W1)*dinv ; x2 = relu(dinv*agg + b1) ----
    k_mma_dinv<FHID, 0><<<nb_gemm, 256>>>(x, W1, n_nodes, FIN);
    k_agg128<<<nb_agg, 256>>>(b1, n_nodes);

    // ---- layer 2: hn = tf32(x2@W2)*dinv ; out = dinv*agg + b2 ----
    k_mma_dinv<FOUT, 1><<<nb_gemm, 256>>>(nullptr, W2, n_nodes, FHID);
    k_agg64<<<nb_agg, 256>>>(b2, out, n_nodes);
}